// round 2
// baseline (speedup 1.0000x reference)
#include <cuda_runtime.h>
#include <math.h>

#define Bq    4
#define Sq    1024
#define Cdim  256
#define INNERq 512
#define NHq   8
#define DHq   64

// ---------------- scratch (static __device__, no allocation) ----------------
__device__ float g_xm[Bq*Sq*INNERq];
__device__ float g_z [Bq*Sq*INNERq];
__device__ float g_xa[Bq*Sq*INNERq];
__device__ float g_q [Bq*Sq*INNERq];
__device__ float g_k [Bq*Sq*INNERq];
__device__ float g_v [Bq*Sq*INNERq];
__device__ float g_ig[Bq*NHq*Sq];
__device__ float g_fg[Bq*NHq*Sq];
__device__ float g_lc[Bq*NHq*Sq];
__device__ float g_h [Bq*Sq*INNERq];

// ---------------- NT GEMM: C[m,n] = sum_k A[m,k]*B[n,k] ----------------
// MODE 0: up-proj   A=x (ext), out -> g_xm | g_z split at 512
// MODE 1: down-proj A=g_h (device global), out -> ext pointer
template<int MODE>
__global__ __launch_bounds__(256) void gemm_nt(
    const float* __restrict__ Aext, const float* __restrict__ Bm,
    float* __restrict__ outext, int Kd)
{
    __shared__ float As[16][65];
    __shared__ float Bs[16][65];
    const float* A = (MODE == 0) ? Aext : g_h;
    int tid = threadIdx.x;
    int m0 = blockIdx.y * 64, n0 = blockIdx.x * 64;
    int ty = tid >> 4, tx = tid & 15;
    int lr  = tid >> 2;          // 0..63 row within tile
    int lc4 = (tid & 3) << 2;    // 0,4,8,12
    float acc[4][4] = {};
    const float* Ap = A  + (size_t)(m0 + lr) * Kd + lc4;
    const float* Bp = Bm + (size_t)(n0 + lr) * Kd + lc4;
    for (int k0 = 0; k0 < Kd; k0 += 16) {
        float4 av = *(const float4*)(Ap + k0);
        float4 bv = *(const float4*)(Bp + k0);
        As[lc4+0][lr] = av.x; As[lc4+1][lr] = av.y; As[lc4+2][lr] = av.z; As[lc4+3][lr] = av.w;
        Bs[lc4+0][lr] = bv.x; Bs[lc4+1][lr] = bv.y; Bs[lc4+2][lr] = bv.z; Bs[lc4+3][lr] = bv.w;
        __syncthreads();
        #pragma unroll
        for (int kk = 0; kk < 16; kk++) {
            float a[4], b[4];
            #pragma unroll
            for (int i = 0; i < 4; i++) { a[i] = As[kk][ty*4+i]; b[i] = Bs[kk][tx*4+i]; }
            #pragma unroll
            for (int i = 0; i < 4; i++)
                #pragma unroll
                for (int j = 0; j < 4; j++) acc[i][j] += a[i] * b[j];
        }
        __syncthreads();
    }
    #pragma unroll
    for (int i = 0; i < 4; i++) {
        int m = m0 + ty*4 + i;
        #pragma unroll
        for (int j = 0; j < 4; j++) {
            int n = n0 + tx*4 + j;
            if (MODE == 0) {
                if (n < INNERq) g_xm[(size_t)m * INNERq + n] = acc[i][j];
                else            g_z [(size_t)m * INNERq + (n - INNERq)] = acc[i][j];
            } else {
                outext[(size_t)m * Cdim + n] = acc[i][j];
            }
        }
    }
}

// ---------------- fused conv + silu + per-block qkv + gate dots ----------------
// grid: B*S blocks of 128 threads; thread t owns 4-channel block n=t
__global__ __launch_bounds__(128) void fused_conv_qkv_gates(
    const float* __restrict__ conv_w, const float* __restrict__ conv_b,
    const float* __restrict__ Wq, const float* __restrict__ Wk, const float* __restrict__ Wv,
    const float* __restrict__ W_i, const float* __restrict__ b_i,
    const float* __restrict__ W_f, const float* __restrict__ b_f)
{
    __shared__ float sh[3 * INNERq];   // [q | k | v]
    int bs = blockIdx.x;
    int b = bs >> 10;
    int s = bs & 1023;
    int t = threadIdx.x;
    size_t rowbase = (size_t)bs * INNERq;

    float xm4[4], xa4[4];
    #pragma unroll
    for (int j = 0; j < 4; j++) {
        int c = t*4 + j;
        float a = conv_b[c];
        #pragma unroll
        for (int kk = 0; kk < 4; kk++) {
            int sp = s - 3 + kk;
            if (sp >= 0) a += g_xm[((size_t)(b*Sq + sp)) * INNERq + c] * conv_w[c*4 + kk];
        }
        float sg = 1.f / (1.f + __expf(-a));
        xa4[j] = a * sg;
        g_xa[rowbase + c] = xa4[j];
        xm4[j] = g_xm[rowbase + c];
    }

    float q4[4], k4[4], v4[4];
    #pragma unroll
    for (int o = 0; o < 4; o++) {
        float aq = 0.f, ak = 0.f, av = 0.f;
        #pragma unroll
        for (int d = 0; d < 4; d++) {
            aq += Wq[t*16 + o*4 + d] * xa4[d];
            ak += Wk[t*16 + o*4 + d] * xa4[d];
            av += Wv[t*16 + o*4 + d] * xm4[d];
        }
        q4[o] = aq; k4[o] = ak; v4[o] = av;
        sh[t*4 + o]            = aq;
        sh[INNERq + t*4 + o]   = ak;
        sh[2*INNERq + t*4 + o] = av;
    }
    *(float4*)&g_q[rowbase + t*4] = make_float4(q4[0], q4[1], q4[2], q4[3]);
    *(float4*)&g_k[rowbase + t*4] = make_float4(k4[0], k4[1], k4[2], k4[3]);
    *(float4*)&g_v[rowbase + t*4] = make_float4(v4[0], v4[1], v4[2], v4[3]);
    __syncthreads();

    // 16 gate dots (8 ig, 8 fg) over gate_in = [q,k,v] (1536)
    int w = t >> 5, l = t & 31;
    #pragma unroll
    for (int g4 = 0; g4 < 4; g4++) {
        int g = w*4 + g4;
        int h = g & 7;
        const float* Wt = (g < 8 ? W_i : W_f) + h * 1536;
        float acc = 0.f;
        for (int idx = l*4; idx < 1536; idx += 128) {
            float4 sv = *(const float4*)&sh[idx];
            float4 wv = *(const float4*)&Wt[idx];
            acc += sv.x*wv.x + sv.y*wv.y + sv.z*wv.z + sv.w*wv.w;
        }
        #pragma unroll
        for (int o = 16; o; o >>= 1) acc += __shfl_xor_sync(0xffffffffu, acc, o);
        if (l == 0) {
            if (g < 8) g_ig[(size_t)(b*NHq + h) * Sq + s] = acc + b_i[h];
            else       g_fg[(size_t)(b*NHq + h) * Sq + s] = acc + b_f[h];
        }
    }
}

// ---------------- log-sigmoid + inclusive cumsum over S per (b,h) ----------------
__global__ __launch_bounds__(1024) void scan_kernel()
{
    int bh = blockIdx.x;
    int s = threadIdx.x;
    float x = g_fg[(size_t)bh * Sq + s];
    float lf = fminf(x, 0.f) - log1pf(expf(-fabsf(x)));
    __shared__ float sc[Sq];
    sc[s] = lf;
    __syncthreads();
    for (int off = 1; off < Sq; off <<= 1) {
        float tv = (s >= off) ? sc[s - off] : 0.f;
        __syncthreads();
        sc[s] += tv;
        __syncthreads();
    }
    g_lc[(size_t)bh * Sq + s] = sc[s];
}

// ---------------- streaming mLSTM attention + LN + skip + silu(z) gate ----------------
// grid (16 row-tiles, 32 bh); 64 threads; thread t owns row i = it*64+t
__global__ __launch_bounds__(64) void attn_kernel(
    const float* __restrict__ norm_w, const float* __restrict__ skipw)
{
    int bh = blockIdx.y;
    int b = bh >> 3, h = bh & 7;
    int it = blockIdx.x;
    int i0 = it * 64;
    int t = threadIdx.x;
    int i = i0 + t;

    __shared__ float ks[64][64];   // broadcast reads only -> no padding needed
    __shared__ float vs[64][64];
    __shared__ float lcj[64], igj[64];

    float qr[64];
    size_t qbase = ((size_t)(b*Sq + i)) * INNERq + h * DHq;
    #pragma unroll
    for (int d4 = 0; d4 < 16; d4++) {
        float4 v = *(const float4*)&g_q[qbase + d4*4];
        qr[d4*4+0] = v.x; qr[d4*4+1] = v.y; qr[d4*4+2] = v.z; qr[d4*4+3] = v.w;
    }
    float lci = g_lc[(size_t)bh * Sq + i];

    float acc[64];
    #pragma unroll
    for (int d = 0; d < 64; d++) acc[d] = 0.f;
    float m = -3.4e38f, ssum = 0.f;

    for (int jt = 0; jt <= it; jt++) {
        int j0 = jt * 64;
        // cooperative coalesced tile load (64 threads x 16 float4)
        #pragma unroll
        for (int e4 = 0; e4 < 16; e4++) {
            int e   = t + 64 * e4;
            int row = e >> 4;
            int c4  = (e & 15) << 2;
            size_t gb = ((size_t)(b*Sq + j0 + row)) * INNERq + h*DHq + c4;
            float4 kv = *(const float4*)&g_k[gb];
            kv.x *= 0.125f; kv.y *= 0.125f; kv.z *= 0.125f; kv.w *= 0.125f;  // 1/sqrt(DH)
            *(float4*)&ks[row][c4] = kv;
            *(float4*)&vs[row][c4] = *(const float4*)&g_v[gb];
        }
        lcj[t] = g_lc[(size_t)bh * Sq + j0 + t];
        igj[t] = g_ig[(size_t)bh * Sq + j0 + t];
        __syncthreads();

        int jmax = min(64, i - j0 + 1);
        if (jmax > 0) {
            // pass 1: tile max of logD (cheap, no dot product)
            float tmax = -3.4e38f;
            for (int jj = 0; jj < jmax; jj++)
                tmax = fmaxf(tmax, lci - lcj[jj] + igj[jj]);
            float mnew = fmaxf(m, tmax);
            if (mnew > m) {
                float sc = __expf(m - mnew);   // exp(-inf)=0 on first tile
                ssum *= sc;
                #pragma unroll
                for (int d = 0; d < 64; d++) acc[d] *= sc;
                m = mnew;
            }
            // pass 2: weighted accumulate (vectorized LDS, broadcast across lanes)
            for (int jj = 0; jj < jmax; jj++) {
                float s0=0.f, s1=0.f, s2=0.f, s3=0.f;
                #pragma unroll
                for (int d = 0; d < 64; d += 4) {
                    float4 kv4 = *(const float4*)&ks[jj][d];
                    s0 += qr[d+0] * kv4.x;
                    s1 += qr[d+1] * kv4.y;
                    s2 += qr[d+2] * kv4.z;
                    s3 += qr[d+3] * kv4.w;
                }
                float sdot = (s0 + s1) + (s2 + s3);
                float wgt = __expf((lci - lcj[jj] + igj[jj]) - m);
                float p = sdot * wgt;
                ssum += p;
                #pragma unroll
                for (int d = 0; d < 64; d += 4) {
                    float4 vv4 = *(const float4*)&vs[jj][d];
                    acc[d+0] += p * vv4.x;
                    acc[d+1] += p * vv4.y;
                    acc[d+2] += p * vv4.z;
                    acc[d+3] += p * vv4.w;
                }
            }
        }
        __syncthreads();
    }

    // epilogue: denom, layernorm over DH, skip, silu(z) gate
    float denom = fmaxf(fabsf(ssum), __expf(-m)) + 1e-6f;
    float inv = 1.f / denom;
    float mean = 0.f;
    #pragma unroll
    for (int d = 0; d < 64; d++) { acc[d] *= inv; mean += acc[d]; }
    mean *= (1.f / 64.f);
    float var = 0.f;
    #pragma unroll
    for (int d = 0; d < 64; d++) { float df = acc[d] - mean; var += df * df; }
    var *= (1.f / 64.f);
    float rstd = rsqrtf(var + 1e-5f);
    size_t obase = ((size_t)(b*Sq + i)) * INNERq + h * DHq;
    #pragma unroll
    for (int d = 0; d < 64; d++) {
        int c = h*DHq + d;
        float hn  = (acc[d] - mean) * rstd * norm_w[c];
        float za  = g_z[obase + d];
        float sil = za / (1.f + __expf(-za));
        g_h[obase + d] = (hn + skipw[c] * g_xa[obase + d]) * sil;
    }
}

// ---------------- launch (kernel launches ONLY — fully graph-capturable) ----------------
extern "C" void kernel_launch(void* const* d_in, const int* in_sizes, int n_in,
                              void* d_out, int out_size)
{
    const float* x      = (const float*)d_in[0];
    const float* W_up   = (const float*)d_in[1];
    const float* conv_w = (const float*)d_in[2];
    const float* conv_b = (const float*)d_in[3];
    const float* Wq     = (const float*)d_in[4];
    const float* Wk     = (const float*)d_in[5];
    const float* Wv     = (const float*)d_in[6];
    const float* W_i    = (const float*)d_in[7];
    const float* b_i    = (const float*)d_in[8];
    const float* W_f    = (const float*)d_in[9];
    const float* b_f    = (const float*)d_in[10];
    const float* norm_w = (const float*)d_in[11];
    const float* skipw  = (const float*)d_in[12];
    const float* W_down = (const float*)d_in[13];
    float* out = (float*)d_out;

    // up: (4096 x 256) @ (1024 x 256)^T -> split x_m | z  (writes device globals)
    gemm_nt<0><<<dim3(16, 64), 256>>>(x, W_up, nullptr, Cdim);
    // conv + silu + qkv + gates
    fused_conv_qkv_gates<<<Bq*Sq, 128>>>(conv_w, conv_b, Wq, Wk, Wv, W_i, b_i, W_f, b_f);
    // log-sigmoid cumsum
    scan_kernel<<<Bq*NHq, 1024>>>();
    // streaming attention + LN + gating
    attn_kernel<<<dim3(Sq/64, Bq*NHq), 64>>>(norm_w, skipw);
    // down: (4096 x 512) @ (256 x 512)^T -> out (reads g_h)
    gemm_nt<1><<<dim3(4, 64), 256>>>(nullptr, W_down, out, INNERq);
}